// round 3
// baseline (speedup 1.0000x reference)
#include <cuda_runtime.h>
#include <cstdint>

#define C_IN   64
#define C_OUT  128
#define KF     27
#define BN_EPS 1e-5f
#define MAX_NV 200000

// ---------------- device scratch (no allocations allowed) ----------------
__device__ __align__(16) float g_agg[(size_t)MAX_NV * C_IN];   // 51.2 MB, zero-init
__device__ __align__(16) float g_sum[C_OUT];                   // BN sums (self-resetting)
__device__ __align__(16) float g_sumsq[C_OUT];
__device__ __align__(16) float g_scale[C_OUT];
__device__ __align__(16) float g_shift[C_OUT];
__device__ int g_vt64;

// vectorized fp32 reduction (sm_90+): 4x fewer RED lane-ops than scalar
__device__ __forceinline__ void red_add_v4(float* p, float4 v) {
    asm volatile("red.global.add.v4.f32 [%0], {%1,%2,%3,%4};"
                 :: "l"(p), "f"(v.x), "f"(v.y), "f"(v.z), "f"(v.w) : "memory");
}

// ---------------- vt_map dtype detection ----------------
// If the buffer is int64 (values < NV < 2^31), every odd int32 word among the
// first 64 elements is 0. For an int32 permutation, the odds of 64 specific
// entries all being zero are nil.
__global__ void detect_vt_kernel(const int* __restrict__ vt32, int nv) {
    int n = nv / 2 < 64 ? nv / 2 : 64;
    int orv = 0;
    for (int e = 0; e < n; ++e) orv |= vt32[2 * e + 1];
    g_vt64 = (orv == 0) ? 1 : 0;
}

// ---------------- stage A: per-face filter mix + scatter ----------------
// Half-warp (16 lanes) per face; lane handles 4 consecutive channels.
__global__ __launch_bounds__(256) void face_kernel(
    const float* __restrict__ inputs, const float* __restrict__ filt,
    const int* __restrict__ face, const float* __restrict__ sw, int nf)
{
    __shared__ float4 s_w[KF * (C_IN / 4)];  // spatial_weights [27][64], 6.9 KB
    for (int i = threadIdx.x; i < KF * (C_IN / 4); i += blockDim.x)
        s_w[i] = ((const float4*)sw)[i];
    __syncthreads();

    const int lane = threadIdx.x & 31;
    const int l16  = lane & 15;
    const int base = lane & 16;              // 0 or 16: start of my half-warp
    const int hw   = (blockIdx.x * blockDim.x + threadIdx.x) >> 4;
    const int nhw  = (gridDim.x * blockDim.x) >> 4;

    for (int f = hw; f < nf; f += nhw) {
        // 27 filter coeffs spread over 16 lanes (2 regs), broadcast via shfl
        float fc0 = filt[(size_t)f * KF + l16];
        float fc1 = (l16 < KF - 16) ? filt[(size_t)f * KF + 16 + l16] : 0.f;
        float4 in4 = ((const float4*)inputs)[(size_t)f * (C_IN / 4) + l16];

        float4 w = make_float4(0.f, 0.f, 0.f, 0.f);
        #pragma unroll
        for (int k = 0; k < KF; ++k) {
            float coef = (k < 16) ? __shfl_sync(0xffffffffu, fc0, base + k)
                                  : __shfl_sync(0xffffffffu, fc1, base + (k - 16));
            float4 s = s_w[k * 16 + l16];
            w.x += coef * s.x; w.y += coef * s.y;
            w.z += coef * s.z; w.w += coef * s.w;
        }
        float4 c4;
        c4.x = in4.x * w.x; c4.y = in4.y * w.y;
        c4.z = in4.z * w.z; c4.w = in4.w * w.w;

        int v0 = face[(size_t)f * 3 + 0];
        int v1 = face[(size_t)f * 3 + 1];
        int v2 = face[(size_t)f * 3 + 2];
        red_add_v4(&g_agg[(size_t)v0 * C_IN + l16 * 4], c4);
        red_add_v4(&g_agg[(size_t)v1 * C_IN + l16 * 4], c4);
        red_add_v4(&g_agg[(size_t)v2 * C_IN + l16 * 4], c4);
    }
}

// ---------------- stage B: gather + 64->128 GEMM + bias + ReLU + BN stats ----------------
#define VB 32   // vertices per tile; each warp owns 8, each thread 4 channels x 8 vertices
__global__ __launch_bounds__(128) void vertex_kernel(
    const void* __restrict__ vt_map, const int* __restrict__ nf_count,
    const float* __restrict__ dw, const float* __restrict__ bias,
    float* __restrict__ out, int nv)
{
    __shared__ float4 s_w4[C_IN * (C_OUT / 4)];  // W row-major [64][128], 32 KB
    __shared__ float  s_a[VB * C_IN];            // 8 KB a-tile (denom applied)
    __shared__ int    s_src[VB];
    __shared__ float  s_inv[VB];
    __shared__ float  s_sum[C_OUT];
    __shared__ float  s_sq[C_OUT];

    const int tid = threadIdx.x;
    for (int i = tid; i < C_IN * (C_OUT / 4); i += 128)
        s_w4[i] = ((const float4*)dw)[i];
    if (tid < C_OUT) { s_sum[tid] = 0.f; s_sq[tid] = 0.f; }

    const int cg = tid & 31;   // channel-group: channels cg*4..cg*4+3
    const int vg = tid >> 5;   // warp id: vertices vg*8..vg*8+7 of the tile
    const float4 b4 = ((const float4*)bias)[cg];
    const int is64 = g_vt64;

    float4 lsum = make_float4(0.f, 0.f, 0.f, 0.f);
    float4 lsq  = make_float4(0.f, 0.f, 0.f, 0.f);

    const int ntiles = (nv + VB - 1) / VB;
    for (int tile = blockIdx.x; tile < ntiles; tile += gridDim.x) {
        const int vbase = tile * VB;
        __syncthreads();  // protect s_a/s_src reuse across tiles
        if (tid < VB) {
            int i = vbase + tid;
            int src = 0; float inv = 0.f;
            if (i < nv) {
                src = is64 ? (int)((const long long*)vt_map)[i]
                           : ((const int*)vt_map)[i];
                int c = nf_count[src];
                inv = 1.0f / (float)(c > 1 ? c : 1);
            }
            s_src[tid] = src; s_inv[tid] = inv;
        }
        __syncthreads();
        #pragma unroll
        for (int rep = 0; rep < (VB * C_IN / 4) / 128; ++rep) {
            int idx = rep * 128 + tid;
            int v = idx >> 4, q = idx & 15;
            float4 a = ((const float4*)g_agg)[(size_t)s_src[v] * (C_IN / 4) + q];
            float inv = s_inv[v];
            a.x *= inv; a.y *= inv; a.z *= inv; a.w *= inv;
            ((float4*)s_a)[v * 16 + q] = a;
        }
        __syncthreads();

        float4 acc[8];
        #pragma unroll
        for (int v = 0; v < 8; ++v) acc[v] = make_float4(0.f, 0.f, 0.f, 0.f);
        const float* av = &s_a[(vg * 8) * C_IN];
        #pragma unroll
        for (int k = 0; k < C_IN; ++k) {
            float4 w = s_w4[k * 32 + cg];
            #pragma unroll
            for (int v = 0; v < 8; ++v) {
                float a = av[v * C_IN + k];
                acc[v].x += a * w.x; acc[v].y += a * w.y;
                acc[v].z += a * w.z; acc[v].w += a * w.w;
            }
        }
        #pragma unroll
        for (int v = 0; v < 8; ++v) {
            int i = vbase + vg * 8 + v;
            if (i < nv) {
                float4 r;
                r.x = fmaxf(acc[v].x + b4.x, 0.f);
                r.y = fmaxf(acc[v].y + b4.y, 0.f);
                r.z = fmaxf(acc[v].z + b4.z, 0.f);
                r.w = fmaxf(acc[v].w + b4.w, 0.f);
                lsum.x += r.x; lsum.y += r.y; lsum.z += r.z; lsum.w += r.w;
                lsq.x += r.x * r.x; lsq.y += r.y * r.y;
                lsq.z += r.z * r.z; lsq.w += r.w * r.w;
                ((float4*)out)[(size_t)i * (C_OUT / 4) + cg] = r;
            }
        }
    }

    // block-level stat reduction, then one global atomic per channel per block
    __syncthreads();
    const int c0 = cg * 4;
    atomicAdd(&s_sum[c0 + 0], lsum.x); atomicAdd(&s_sum[c0 + 1], lsum.y);
    atomicAdd(&s_sum[c0 + 2], lsum.z); atomicAdd(&s_sum[c0 + 3], lsum.w);
    atomicAdd(&s_sq[c0 + 0], lsq.x);   atomicAdd(&s_sq[c0 + 1], lsq.y);
    atomicAdd(&s_sq[c0 + 2], lsq.z);   atomicAdd(&s_sq[c0 + 3], lsq.w);
    __syncthreads();
    if (tid < C_OUT) {
        atomicAdd(&g_sum[tid], s_sum[tid]);
        atomicAdd(&g_sumsq[tid], s_sq[tid]);
    }
}

// ---------------- BN finalize: scale/shift per channel; reset stats ----------------
__global__ void finalize_kernel(const float* __restrict__ gamma,
                                const float* __restrict__ beta, float inv_n)
{
    int c = threadIdx.x;
    if (c < C_OUT) {
        float mean = g_sum[c] * inv_n;
        float var  = fmaxf(g_sumsq[c] * inv_n - mean * mean, 0.f);
        float sc   = rsqrtf(var + BN_EPS) * gamma[c];
        g_scale[c] = sc;
        g_shift[c] = beta[c] - mean * sc;
        g_sum[c] = 0.f; g_sumsq[c] = 0.f;  // deterministic across launches
    }
}

// ---------------- BN apply ----------------
__global__ __launch_bounds__(256) void bn_kernel(float* __restrict__ out, int n4) {
    int idx = blockIdx.x * blockDim.x + threadIdx.x;
    int stride = gridDim.x * blockDim.x;
    for (int i = idx; i < n4; i += stride) {
        int cg = i & ((C_OUT / 4) - 1);
        float4 v  = ((float4*)out)[i];
        float4 sc = ((const float4*)g_scale)[cg];
        float4 sh = ((const float4*)g_shift)[cg];
        v.x = v.x * sc.x + sh.x; v.y = v.y * sc.y + sh.y;
        v.z = v.z * sc.z + sh.z; v.w = v.w * sc.w + sh.w;
        ((float4*)out)[i] = v;
    }
}

// ---------------- launch ----------------
extern "C" void kernel_launch(void* const* d_in, const int* in_sizes, int n_in,
                              void* d_out, int out_size) {
    const float* inputs   = (const float*)d_in[0];   // [NF,64]
    const float* filt     = (const float*)d_in[1];   // [NF,27]
    const int*   face     = (const int*)d_in[2];     // [NF,3]
    const int*   nf_count = (const int*)d_in[3];     // [NV]
    const void*  vt_map   = d_in[4];                 // [NV] int32 or int64
    const float* sw       = (const float*)d_in[5];   // [27,64,1]
    const float* dw       = (const float*)d_in[6];   // [64,128]
    const float* bias     = (const float*)d_in[7];   // [1,128]
    const float* gamma    = (const float*)d_in[8];   // [128]
    const float* beta     = (const float*)d_in[9];   // [128]
    float* out = (float*)d_out;

    const int nf = in_sizes[0] / C_IN;
    const int nv = in_sizes[3];

    void* aggp = nullptr;
    cudaGetSymbolAddress(&aggp, g_agg);
    cudaMemsetAsync(aggp, 0, (size_t)nv * C_IN * sizeof(float));

    detect_vt_kernel<<<1, 1>>>((const int*)vt_map, nv);
    face_kernel<<<2048, 256>>>(inputs, filt, face, sw, nf);
    vertex_kernel<<<1480, 128>>>(vt_map, nf_count, dw, bias, out, nv);
    finalize_kernel<<<1, C_OUT>>>(gamma, beta, 1.0f / (float)nv);

    int n4 = nv * (C_OUT / 4);
    bn_kernel<<<4096, 256>>>(out, n4);
}

// round 4
// speedup vs baseline: 1.0276x; 1.0276x over previous
#include <cuda_runtime.h>
#include <cstdint>

#define C_IN   64
#define C_OUT  128
#define KF     27
#define BN_EPS 1e-5f
#define MAX_NV 200000

// ---------------- device scratch (no allocations allowed) ----------------
__device__ __align__(16) float g_agg[(size_t)MAX_NV * C_IN];   // 51.2 MB, zero-init
__device__ __align__(16) float g_sum[C_OUT];                   // BN sums (self-resetting)
__device__ __align__(16) float g_sumsq[C_OUT];
__device__ __align__(16) float g_scale[C_OUT];
__device__ __align__(16) float g_shift[C_OUT];
__device__ int g_vt64;

// vectorized fp32 reduction (sm_90+): 4x fewer RED lane-ops than scalar
__device__ __forceinline__ void red_add_v4(float* p, float4 v) {
    asm volatile("red.global.add.v4.f32 [%0], {%1,%2,%3,%4};"
                 :: "l"(p), "f"(v.x), "f"(v.y), "f"(v.z), "f"(v.w) : "memory");
}

// ---- packed f32x2 helpers (FFMA2: 2 FMA lanes/issue, 2x fp32 fma throughput) ----
__device__ __forceinline__ unsigned long long pack2(float lo, float hi) {
    unsigned long long r;
    asm("mov.b64 %0, {%1, %2};" : "=l"(r) : "f"(lo), "f"(hi));
    return r;
}
__device__ __forceinline__ void fma2(unsigned long long& acc,
                                     unsigned long long a, unsigned long long b) {
    asm("fma.rn.f32x2 %0, %1, %2, %0;" : "+l"(acc) : "l"(a), "l"(b));
}
__device__ __forceinline__ void unpack2(float& lo, float& hi, unsigned long long v) {
    asm("mov.b64 {%0, %1}, %2;" : "=f"(lo), "=f"(hi) : "l"(v));
}

// ---------------- vt_map dtype detection ----------------
// If the buffer holds int64 (values < NV < 2^31) every odd int32 word is 0.
__global__ void detect_vt_kernel(const int* __restrict__ vt32, int nv) {
    int n = nv / 2 < 32 ? nv / 2 : 32;
    int v = (threadIdx.x < n) ? vt32[2 * threadIdx.x + 1] : 0;
    unsigned nz = __ballot_sync(0xffffffffu, v != 0);
    if (threadIdx.x == 0) g_vt64 = (nz == 0u) ? 1 : 0;
}

// ---------------- stage A: per-face filter mix + scatter ----------------
// Half-warp (16 lanes) per face; lane handles 4 consecutive channels.
__global__ __launch_bounds__(256) void face_kernel(
    const float* __restrict__ inputs, const float* __restrict__ filt,
    const int* __restrict__ face, const float* __restrict__ sw, int nf)
{
    __shared__ float4 s_w[KF * (C_IN / 4)];  // spatial_weights [27][64], 6.9 KB
    for (int i = threadIdx.x; i < KF * (C_IN / 4); i += blockDim.x)
        s_w[i] = ((const float4*)sw)[i];
    __syncthreads();

    const int lane = threadIdx.x & 31;
    const int l16  = lane & 15;
    const int base = lane & 16;              // 0 or 16: start of my half-warp
    const int hw   = (blockIdx.x * blockDim.x + threadIdx.x) >> 4;
    const int nhw  = (gridDim.x * blockDim.x) >> 4;

    for (int f = hw; f < nf; f += nhw) {
        float fc0 = filt[(size_t)f * KF + l16];
        float fc1 = (l16 < KF - 16) ? filt[(size_t)f * KF + 16 + l16] : 0.f;
        float4 in4 = ((const float4*)inputs)[(size_t)f * (C_IN / 4) + l16];

        float4 w = make_float4(0.f, 0.f, 0.f, 0.f);
        #pragma unroll
        for (int k = 0; k < KF; ++k) {
            float coef = (k < 16) ? __shfl_sync(0xffffffffu, fc0, base + k)
                                  : __shfl_sync(0xffffffffu, fc1, base + (k - 16));
            float4 s = s_w[k * 16 + l16];
            w.x += coef * s.x; w.y += coef * s.y;
            w.z += coef * s.z; w.w += coef * s.w;
        }
        float4 c4;
        c4.x = in4.x * w.x; c4.y = in4.y * w.y;
        c4.z = in4.z * w.z; c4.w = in4.w * w.w;

        int v0 = face[(size_t)f * 3 + 0];
        int v1 = face[(size_t)f * 3 + 1];
        int v2 = face[(size_t)f * 3 + 2];
        red_add_v4(&g_agg[(size_t)v0 * C_IN + l16 * 4], c4);
        red_add_v4(&g_agg[(size_t)v1 * C_IN + l16 * 4], c4);
        red_add_v4(&g_agg[(size_t)v2 * C_IN + l16 * 4], c4);
    }
}

// ---------------- stage B: gather + 64->128 GEMM + bias + ReLU + BN stats ----------------
#define VB 32   // vertices per tile; each warp owns 8, each thread 4 channels x 8 vertices
__global__ __launch_bounds__(128) void vertex_kernel(
    const void* __restrict__ vt_map, const int* __restrict__ nf_count,
    const float* __restrict__ dw, const float* __restrict__ bias,
    float* __restrict__ out, int nv)
{
    __shared__ float4 s_w4[C_IN * (C_OUT / 4)];  // W row-major [64][128], 32 KB
    __shared__ float  s_a[VB * C_IN];            // 8 KB a-tile (denom applied)
    __shared__ int    s_src[VB];
    __shared__ float  s_inv[VB];
    __shared__ float  s_sum[C_OUT];
    __shared__ float  s_sq[C_OUT];

    const int tid = threadIdx.x;
    for (int i = tid; i < C_IN * (C_OUT / 4); i += 128)
        s_w4[i] = ((const float4*)dw)[i];
    if (tid < C_OUT) { s_sum[tid] = 0.f; s_sq[tid] = 0.f; }

    const int cg = tid & 31;   // channel-group: channels cg*4..cg*4+3
    const int vg = tid >> 5;   // warp id: vertices vg*8..vg*8+7 of the tile
    const float4 b4 = ((const float4*)bias)[cg];
    const int is64 = g_vt64;
    // view W as pairs: w2[k*32+cg] = { {w[c0],w[c0+1]}, {w[c0+2],w[c0+3]} }
    const ulonglong2* s_w2 = (const ulonglong2*)s_w4;

    float4 lsum = make_float4(0.f, 0.f, 0.f, 0.f);
    float4 lsq  = make_float4(0.f, 0.f, 0.f, 0.f);

    const int ntiles = (nv + VB - 1) / VB;
    for (int tile = blockIdx.x; tile < ntiles; tile += gridDim.x) {
        const int vbase = tile * VB;
        __syncthreads();  // protect s_a/s_src reuse across tiles
        if (tid < VB) {
            int i = vbase + tid;
            int src = 0; float inv = 0.f;
            if (i < nv) {
                src = is64 ? (int)((const long long*)vt_map)[i]
                           : ((const int*)vt_map)[i];
                int c = nf_count[src];
                inv = 1.0f / (float)(c > 1 ? c : 1);
            }
            s_src[tid] = src; s_inv[tid] = inv;
        }
        __syncthreads();
        #pragma unroll
        for (int rep = 0; rep < (VB * C_IN / 4) / 128; ++rep) {
            int idx = rep * 128 + tid;
            int v = idx >> 4, q = idx & 15;
            float4 a = ((const float4*)g_agg)[(size_t)s_src[v] * (C_IN / 4) + q];
            float inv = s_inv[v];
            a.x *= inv; a.y *= inv; a.z *= inv; a.w *= inv;
            ((float4*)s_a)[v * 16 + q] = a;
        }
        __syncthreads();

        // 8 vertices x 4 channels per thread, packed-f32x2 accumulators
        unsigned long long acc[8][2];
        #pragma unroll
        for (int v = 0; v < 8; ++v) { acc[v][0] = 0ull; acc[v][1] = 0ull; }
        const float* av = &s_a[(vg * 8) * C_IN];
        #pragma unroll
        for (int k = 0; k < C_IN; ++k) {
            ulonglong2 w = s_w2[k * 32 + cg];
            #pragma unroll
            for (int v = 0; v < 8; ++v) {
                float a = av[v * C_IN + k];
                unsigned long long ap = pack2(a, a);
                fma2(acc[v][0], ap, w.x);
                fma2(acc[v][1], ap, w.y);
            }
        }
        #pragma unroll
        for (int v = 0; v < 8; ++v) {
            int i = vbase + vg * 8 + v;
            if (i < nv) {
                float4 r;
                unpack2(r.x, r.y, acc[v][0]);
                unpack2(r.z, r.w, acc[v][1]);
                r.x = fmaxf(r.x + b4.x, 0.f);
                r.y = fmaxf(r.y + b4.y, 0.f);
                r.z = fmaxf(r.z + b4.z, 0.f);
                r.w = fmaxf(r.w + b4.w, 0.f);
                lsum.x += r.x; lsum.y += r.y; lsum.z += r.z; lsum.w += r.w;
                lsq.x += r.x * r.x; lsq.y += r.y * r.y;
                lsq.z += r.z * r.z; lsq.w += r.w * r.w;
                ((float4*)out)[(size_t)i * (C_OUT / 4) + cg] = r;
            }
        }
    }

    // block-level stat reduction, then one global atomic per channel per block
    __syncthreads();
    const int c0 = cg * 4;
    atomicAdd(&s_sum[c0 + 0], lsum.x); atomicAdd(&s_sum[c0 + 1], lsum.y);
    atomicAdd(&s_sum[c0 + 2], lsum.z); atomicAdd(&s_sum[c0 + 3], lsum.w);
    atomicAdd(&s_sq[c0 + 0], lsq.x);   atomicAdd(&s_sq[c0 + 1], lsq.y);
    atomicAdd(&s_sq[c0 + 2], lsq.z);   atomicAdd(&s_sq[c0 + 3], lsq.w);
    __syncthreads();
    if (tid < C_OUT) {
        atomicAdd(&g_sum[tid], s_sum[tid]);
        atomicAdd(&g_sumsq[tid], s_sq[tid]);
    }
}

// ---------------- BN finalize: scale/shift per channel; reset stats ----------------
__global__ void finalize_kernel(const float* __restrict__ gamma,
                                const float* __restrict__ beta, float inv_n)
{
    int c = threadIdx.x;
    if (c < C_OUT) {
        float mean = g_sum[c] * inv_n;
        float var  = fmaxf(g_sumsq[c] * inv_n - mean * mean, 0.f);
        float sc   = rsqrtf(var + BN_EPS) * gamma[c];
        g_scale[c] = sc;
        g_shift[c] = beta[c] - mean * sc;
        g_sum[c] = 0.f; g_sumsq[c] = 0.f;  // deterministic across launches
    }
}

// ---------------- BN apply ----------------
__global__ __launch_bounds__(256) void bn_kernel(float* __restrict__ out, int n4) {
    int idx = blockIdx.x * blockDim.x + threadIdx.x;
    int stride = gridDim.x * blockDim.x;
    for (int i = idx; i < n4; i += stride) {
        int cg = i & ((C_OUT / 4) - 1);
        float4 v  = ((float4*)out)[i];
        float4 sc = ((const float4*)g_scale)[cg];
        float4 sh = ((const float4*)g_shift)[cg];
        v.x = v.x * sc.x + sh.x; v.y = v.y * sc.y + sh.y;
        v.z = v.z * sc.z + sh.z; v.w = v.w * sc.w + sh.w;
        ((float4*)out)[i] = v;
    }
}

// ---------------- launch ----------------
extern "C" void kernel_launch(void* const* d_in, const int* in_sizes, int n_in,
                              void* d_out, int out_size) {
    const float* inputs   = (const float*)d_in[0];   // [NF,64]
    const float* filt     = (const float*)d_in[1];   // [NF,27]
    const int*   face     = (const int*)d_in[2];     // [NF,3]
    const int*   nf_count = (const int*)d_in[3];     // [NV]
    const void*  vt_map   = d_in[4];                 // [NV] int32 or int64
    const float* sw       = (const float*)d_in[5];   // [27,64,1]
    const float* dw       = (const float*)d_in[6];   // [64,128]
    const float* bias     = (const float*)d_in[7];   // [1,128]
    const float* gamma    = (const float*)d_in[8];   // [128]
    const float* beta     = (const float*)d_in[9];   // [128]
    float* out = (float*)d_out;

    const int nf = in_sizes[0] / C_IN;
    const int nv = in_sizes[3];

    void* aggp = nullptr;
    cudaGetSymbolAddress(&aggp, g_agg);
    cudaMemsetAsync(aggp, 0, (size_t)nv * C_IN * sizeof(float));

    detect_vt_kernel<<<1, 32>>>((const int*)vt_map, nv);
    face_kernel<<<2048, 256>>>(inputs, filt, face, sw, nf);
    vertex_kernel<<<1480, 128>>>(vt_map, nf_count, dw, bias, out, nv);
    finalize_kernel<<<1, C_OUT>>>(gamma, beta, 1.0f / (float)nv);

    int n4 = nv * (C_OUT / 4);
    bn_kernel<<<4096, 256>>>(out, n4);
}